// round 3
// baseline (speedup 1.0000x reference)
#include <cuda_runtime.h>

#define Tn 4096   // B*S tokens
#define Dn 1024
#define En 8
#define Fn 4096
#define Bb 8
#define Sn 512

// ---------------- scratch (device globals; no allocations) ----------------
__device__ float g_lin[Tn * Dn];          // 16 MB
__device__ float g_accb[Tn * Dn];         // x + moe accum, 16 MB
__device__ float g_h[2 * Tn * Fn];        // 128 MB hidden activations
__device__ int   g_tok[2 * Tn];
__device__ float g_tw[2 * Tn];
__device__ int   g_cnt[En];
__device__ int   g_off[En];
__device__ int   g_fill[En];
__device__ int   g_gi[Tn * 2];
__device__ float g_gw[Tn * 2];
__device__ float g_sent[Bb * Dn];

// ---------------- init: acc = x, zero expert counters ----------------
__global__ void k_init(const float* __restrict__ x) {
    if (blockIdx.x == 0 && threadIdx.x < En) g_cnt[threadIdx.x] = 0;
    int stride = gridDim.x * blockDim.x;
    for (int i = blockIdx.x * blockDim.x + threadIdx.x; i < Tn * Dn; i += stride)
        g_accb[i] = x[i];
}

// ---------------- GEMM: lin = x @ W^T + b   (M=4096,N=1024,K=1024, B is NT) --
__global__ void __launch_bounds__(256) k_gemm_lin(
    const float* __restrict__ x, const float* __restrict__ W,
    const float* __restrict__ bias)
{
    __shared__ float As[16][132];
    __shared__ float Bs[16][132];
    int row0 = blockIdx.y * 128, col0 = blockIdx.x * 128;
    int tid = threadIdx.x;
    int rA = tid >> 2;           // 0..63
    int k4 = (tid & 3) * 4;
    int ty = tid >> 4, tx = tid & 15;
    float cc[8][8] = {};
    for (int k0 = 0; k0 < Dn; k0 += 16) {
        // A tile 128x16 -> As[k][m] (two rows per thread: rA, rA+64)
        float4 va = *(const float4*)&x[(size_t)(row0 + rA) * Dn + k0 + k4];
        As[k4 + 0][rA] = va.x; As[k4 + 1][rA] = va.y;
        As[k4 + 2][rA] = va.z; As[k4 + 3][rA] = va.w;
        float4 vb = *(const float4*)&x[(size_t)(row0 + rA + 64) * Dn + k0 + k4];
        As[k4 + 0][rA + 64] = vb.x; As[k4 + 1][rA + 64] = vb.y;
        As[k4 + 2][rA + 64] = vb.z; As[k4 + 3][rA + 64] = vb.w;
        // B tile: W[n][k] (NT) -> Bs[k][n]
        float4 w0 = *(const float4*)&W[(size_t)(col0 + rA) * Dn + k0 + k4];
        Bs[k4 + 0][rA] = w0.x; Bs[k4 + 1][rA] = w0.y;
        Bs[k4 + 2][rA] = w0.z; Bs[k4 + 3][rA] = w0.w;
        float4 w1v = *(const float4*)&W[(size_t)(col0 + rA + 64) * Dn + k0 + k4];
        Bs[k4 + 0][rA + 64] = w1v.x; Bs[k4 + 1][rA + 64] = w1v.y;
        Bs[k4 + 2][rA + 64] = w1v.z; Bs[k4 + 3][rA + 64] = w1v.w;
        __syncthreads();
#pragma unroll
        for (int k = 0; k < 16; k++) {
            float4 a0 = *(float4*)&As[k][ty * 8], a1 = *(float4*)&As[k][ty * 8 + 4];
            float4 b0 = *(float4*)&Bs[k][tx * 8], b1 = *(float4*)&Bs[k][tx * 8 + 4];
            float ra[8] = {a0.x, a0.y, a0.z, a0.w, a1.x, a1.y, a1.z, a1.w};
            float rb[8] = {b0.x, b0.y, b0.z, b0.w, b1.x, b1.y, b1.z, b1.w};
#pragma unroll
            for (int i = 0; i < 8; i++)
#pragma unroll
                for (int j = 0; j < 8; j++) cc[i][j] += ra[i] * rb[j];
        }
        __syncthreads();
    }
#pragma unroll
    for (int i = 0; i < 8; i++) {
        int row = row0 + ty * 8 + i;
        float* c = &g_lin[(size_t)row * Dn + col0 + tx * 8];
#pragma unroll
        for (int j = 0; j < 8; j++) c[j] = cc[i][j] + bias[col0 + tx * 8 + j];
    }
}

// ---------------- gate: softmax top-2, renormalized -> weights + counts -----
__global__ void k_gate(const float* __restrict__ Wg) {
    int warp = (blockIdx.x * blockDim.x + threadIdx.x) >> 5;
    int lane = threadIdx.x & 31;
    if (warp >= Tn) return;
    const float* lr = &g_lin[(size_t)warp * Dn];
    float p[En];
#pragma unroll
    for (int e = 0; e < En; e++) p[e] = 0.f;
    for (int i = lane; i < Dn; i += 32) {
        float v = lr[i];
        const float* w = &Wg[i * En];
#pragma unroll
        for (int e = 0; e < En; e++) p[e] += v * w[e];
    }
#pragma unroll
    for (int o = 16; o; o >>= 1)
#pragma unroll
        for (int e = 0; e < En; e++) p[e] += __shfl_xor_sync(0xffffffffu, p[e], o);
    if (lane == 0) {
        int i1 = 0;
        for (int e = 1; e < En; e++) if (p[e] > p[i1]) i1 = e;
        int i2 = -1;
        for (int e = 0; e < En; e++)
            if (e != i1 && (i2 < 0 || p[e] > p[i2])) i2 = e;
        // renormalized top-2 softmax: Z cancels
        float w1 = 1.f / (1.f + expf(p[i2] - p[i1]));
        g_gi[warp * 2] = i1; g_gi[warp * 2 + 1] = i2;
        g_gw[warp * 2] = w1; g_gw[warp * 2 + 1] = 1.f - w1;
        atomicAdd(&g_cnt[i1], 1);
        atomicAdd(&g_cnt[i2], 1);
    }
}

// ---------------- prefix offsets + reset fill ----------------
__global__ void k_off() {
    int a = 0;
    for (int e = 0; e < En; e++) { g_off[e] = a; a += g_cnt[e]; g_fill[e] = 0; }
}

// ---------------- scatter token lists ----------------
__global__ void k_scatter() {
    int t = blockIdx.x * blockDim.x + threadIdx.x;
    if (t >= Tn) return;
#pragma unroll
    for (int k = 0; k < 2; k++) {
        int e = g_gi[t * 2 + k];
        int pos = atomicAdd(&g_fill[e], 1);
        int slot = g_off[e] + pos;
        g_tok[slot] = t;
        g_tw[slot]  = g_gw[t * 2 + k];
    }
}

// ---- grouped GEMM1: h = relu(lin_gathered @ w1[e] + b1[e])  (K=1024,N=4096) -
__global__ void __launch_bounds__(256) k_ffn1(
    const float* __restrict__ w1, const float* __restrict__ b1)
{
    __shared__ float As[16][132];
    __shared__ float Bs[16][132];
    int e = blockIdx.z;
    int cnt = g_cnt[e];
    int row0 = blockIdx.y * 128;
    if (row0 >= cnt) return;
    int off = g_off[e];
    int col0 = blockIdx.x * 128;
    int tid = threadIdx.x;
    int rA = tid >> 2;
    int k4 = (tid & 3) * 4;
    int ty = tid >> 4, tx = tid & 15;
    bool v0 = (row0 + rA) < cnt, v1 = (row0 + rA + 64) < cnt;
    const float* a0p = v0 ? &g_lin[(size_t)g_tok[off + row0 + rA] * Dn] : g_lin;
    const float* a1p = v1 ? &g_lin[(size_t)g_tok[off + row0 + rA + 64] * Dn] : g_lin;
    const float* wp = w1 + (size_t)e * Dn * Fn;
    float cc[8][8] = {};
    for (int k0 = 0; k0 < Dn; k0 += 16) {
        float4 va = v0 ? *(const float4*)&a0p[k0 + k4] : make_float4(0, 0, 0, 0);
        As[k4 + 0][rA] = va.x; As[k4 + 1][rA] = va.y;
        As[k4 + 2][rA] = va.z; As[k4 + 3][rA] = va.w;
        float4 vb = v1 ? *(const float4*)&a1p[k0 + k4] : make_float4(0, 0, 0, 0);
        As[k4 + 0][rA + 64] = vb.x; As[k4 + 1][rA + 64] = vb.y;
        As[k4 + 2][rA + 64] = vb.z; As[k4 + 3][rA + 64] = vb.w;
#pragma unroll
        for (int l = 0; l < 2; l++) {
            int idx = tid + l * 256;
            int r = idx >> 5, c4 = (idx & 31) * 4;
            *(float4*)&Bs[r][c4] =
                *(const float4*)&wp[(size_t)(k0 + r) * Fn + col0 + c4];
        }
        __syncthreads();
#pragma unroll
        for (int k = 0; k < 16; k++) {
            float4 a0 = *(float4*)&As[k][ty * 8], a1 = *(float4*)&As[k][ty * 8 + 4];
            float4 b0 = *(float4*)&Bs[k][tx * 8], b1v = *(float4*)&Bs[k][tx * 8 + 4];
            float ra[8] = {a0.x, a0.y, a0.z, a0.w, a1.x, a1.y, a1.z, a1.w};
            float rb[8] = {b0.x, b0.y, b0.z, b0.w, b1v.x, b1v.y, b1v.z, b1v.w};
#pragma unroll
            for (int i = 0; i < 8; i++)
#pragma unroll
                for (int j = 0; j < 8; j++) cc[i][j] += ra[i] * rb[j];
        }
        __syncthreads();
    }
#pragma unroll
    for (int i = 0; i < 8; i++) {
        int row = row0 + ty * 8 + i;
        if (row < cnt) {
            int slot = off + row;
            float* c = &g_h[(size_t)slot * Fn + col0 + tx * 8];
#pragma unroll
            for (int j = 0; j < 8; j++)
                c[j] = fmaxf(cc[i][j] + b1[e * Fn + col0 + tx * 8 + j], 0.f);
        }
    }
}

// ---- grouped GEMM2: acc += gate_w * (h @ w2[e] + b2[e])  (K=4096,N=1024) ----
__global__ void __launch_bounds__(256) k_ffn2(
    const float* __restrict__ w2, const float* __restrict__ b2)
{
    __shared__ float As[16][132];
    __shared__ float Bs[16][132];
    int e = blockIdx.z;
    int cnt = g_cnt[e];
    int row0 = blockIdx.y * 128;
    if (row0 >= cnt) return;
    int off = g_off[e];
    int col0 = blockIdx.x * 128;
    int tid = threadIdx.x;
    int rA = tid >> 2;
    int k4 = (tid & 3) * 4;
    int ty = tid >> 4, tx = tid & 15;
    bool v0 = (row0 + rA) < cnt, v1 = (row0 + rA + 64) < cnt;
    const float* a0p = &g_h[(size_t)(off + row0 + rA) * Fn];
    const float* a1p = &g_h[(size_t)(off + row0 + rA + 64 < 2 * Tn ? off + row0 + rA + 64 : 0) * Fn];
    const float* wp = w2 + (size_t)e * Fn * Dn;
    float cc[8][8] = {};
    for (int k0 = 0; k0 < Fn; k0 += 16) {
        float4 va = v0 ? *(const float4*)&a0p[k0 + k4] : make_float4(0, 0, 0, 0);
        As[k4 + 0][rA] = va.x; As[k4 + 1][rA] = va.y;
        As[k4 + 2][rA] = va.z; As[k4 + 3][rA] = va.w;
        float4 vb = v1 ? *(const float4*)&a1p[k0 + k4] : make_float4(0, 0, 0, 0);
        As[k4 + 0][rA + 64] = vb.x; As[k4 + 1][rA + 64] = vb.y;
        As[k4 + 2][rA + 64] = vb.z; As[k4 + 3][rA + 64] = vb.w;
#pragma unroll
        for (int l = 0; l < 2; l++) {
            int idx = tid + l * 256;
            int r = idx >> 5, c4 = (idx & 31) * 4;
            *(float4*)&Bs[r][c4] =
                *(const float4*)&wp[(size_t)(k0 + r) * Dn + col0 + c4];
        }
        __syncthreads();
#pragma unroll
        for (int k = 0; k < 16; k++) {
            float4 a0 = *(float4*)&As[k][ty * 8], a1 = *(float4*)&As[k][ty * 8 + 4];
            float4 b0 = *(float4*)&Bs[k][tx * 8], b1v = *(float4*)&Bs[k][tx * 8 + 4];
            float ra[8] = {a0.x, a0.y, a0.z, a0.w, a1.x, a1.y, a1.z, a1.w};
            float rb[8] = {b0.x, b0.y, b0.z, b0.w, b1v.x, b1v.y, b1v.z, b1v.w};
#pragma unroll
            for (int i = 0; i < 8; i++)
#pragma unroll
                for (int j = 0; j < 8; j++) cc[i][j] += ra[i] * rb[j];
        }
        __syncthreads();
    }
#pragma unroll
    for (int i = 0; i < 8; i++) {
        int row = row0 + ty * 8 + i;
        if (row < cnt) {
            int slot = off + row;
            int token = g_tok[slot];
            float gw = g_tw[slot];
            float* c = &g_accb[(size_t)token * Dn + col0 + tx * 8];
#pragma unroll
            for (int j = 0; j < 8; j++)
                atomicAdd(&c[j], gw * (cc[i][j] + b2[e * Dn + col0 + tx * 8 + j]));
        }
    }
}

// ---------------- mean pool over sequence ----------------
__global__ void k_sent(float* out) {
    int i = blockIdx.x * blockDim.x + threadIdx.x;
    if (i == 0) out[0] = 0.f;  // zero the scalar output (stream-ordered before k_loss)
    if (i >= Bb * Dn) return;
    int b = i >> 10, d = i & 1023;
    const float* p = &g_accb[(size_t)(b * Sn) * Dn + d];
    float s = 0.f;
    for (int si = 0; si < Sn; si++) s += p[si * Dn];
    g_sent[i] = s * (1.f / Sn);
}

// ---------------- log-softmax cross-entropy ----------------
__global__ void k_loss(const int* __restrict__ y, float* out) {
    int b = blockIdx.x, tid = threadIdx.x;
    __shared__ float red[256];
    const float* s = &g_sent[b * Dn];
    float m = -1e30f;
    for (int i = tid; i < Dn; i += 256) m = fmaxf(m, s[i]);
    red[tid] = m; __syncthreads();
    for (int o = 128; o; o >>= 1) {
        if (tid < o) red[tid] = fmaxf(red[tid], red[tid + o]);
        __syncthreads();
    }
    float mx = red[0]; __syncthreads();
    float sum = 0.f;
    for (int i = tid; i < Dn; i += 256) sum += expf(s[i] - mx);
    red[tid] = sum; __syncthreads();
    for (int o = 128; o; o >>= 1) {
        if (tid < o) red[tid] += red[tid + o];
        __syncthreads();
    }
    if (tid == 0) {
        float lse = mx + logf(red[0]);
        float tgt = s[y[b]];
        atomicAdd(out, -(tgt - lse) * (1.f / Bb));
    }
}

// ---------------- launch ----------------
extern "C" void kernel_launch(void* const* d_in, const int* in_sizes, int n_in,
                              void* d_out, int out_size) {
    const float* x  = (const float*)d_in[0];
    const int*   y  = (const int*)d_in[1];
    const float* W  = (const float*)d_in[2];
    const float* bb = (const float*)d_in[3];
    const float* Wg = (const float*)d_in[4];
    const float* w1 = (const float*)d_in[5];
    const float* b1 = (const float*)d_in[6];
    const float* w2 = (const float*)d_in[7];
    const float* b2 = (const float*)d_in[8];
    float* out = (float*)d_out;

    k_init<<<256, 256>>>(x);
    dim3 gl(Dn / 128, Tn / 128);
    k_gemm_lin<<<gl, 256>>>(x, W, bb);
    k_gate<<<(Tn * 32) / 256, 256>>>(Wg);
    k_off<<<1, 1>>>();
    k_scatter<<<Tn / 256, 256>>>();
    dim3 g1(Fn / 128, Tn / 128, En);   // row tiles sized for worst-case routing
    k_ffn1<<<g1, 256>>>(w1, b1);
    dim3 g2(Dn / 128, Tn / 128, En);
    k_ffn2<<<g2, 256>>>(w2, b2);
    k_sent<<<(Bb * Dn + 255) / 256, 256>>>(out);
    k_loss<<<Bb, 256>>>(y, out);
}

// round 5
// speedup vs baseline: 2.2933x; 2.2933x over previous
#include <cuda_runtime.h>
#include <cstdint>

#define Tn 4096   // B*S tokens
#define Dn 1024
#define En 8
#define Fn 4096
#define Bb 8
#define Sn 512

// ---------------- scratch (device globals; no allocations) ----------------
__device__ float g_lin[Tn * Dn];
__device__ float g_accb[Tn * Dn];
__device__ float g_h[2 * Tn * Fn];
__device__ int   g_tok[2 * Tn];
__device__ float g_tw[2 * Tn];
__device__ int   g_cnt[En], g_off[En], g_fill[En];
__device__ int   g_gi[Tn * 2];
__device__ float g_gw[Tn * 2];
__device__ float g_sent[Bb * Dn];

// ---------------- tf32 helpers ----------------
__device__ __forceinline__ float tf32r(float v) {
    uint32_t r;
    asm("cvt.rna.tf32.f32 %0, %1;" : "=r"(r) : "f"(v));
    return __uint_as_float(r);
}
__device__ __forceinline__ void mma8(float* c, const uint32_t* a,
                                     uint32_t b0, uint32_t b1) {
    asm volatile(
        "mma.sync.aligned.m16n8k8.row.col.f32.tf32.tf32.f32 "
        "{%0,%1,%2,%3},{%4,%5,%6,%7},{%8,%9},{%0,%1,%2,%3};"
        : "+f"(c[0]), "+f"(c[1]), "+f"(c[2]), "+f"(c[3])
        : "r"(a[0]), "r"(a[1]), "r"(a[2]), "r"(a[3]), "r"(b0), "r"(b1));
}

// ---------------- init: acc = x, zero expert counters ----------------
__global__ void k_init(const float* __restrict__ x) {
    if (blockIdx.x == 0 && threadIdx.x < En) g_cnt[threadIdx.x] = 0;
    int st = gridDim.x * blockDim.x;
    for (int i = blockIdx.x * blockDim.x + threadIdx.x; i < Tn * Dn; i += st)
        g_accb[i] = x[i];
}

// ---------------- lin = x @ W^T + b (fp32 exact; feeds gate) ----------------
__global__ void __launch_bounds__(256) k_gemm_lin(
    const float* __restrict__ x, const float* __restrict__ W,
    const float* __restrict__ bias)
{
    __shared__ float As[16][132];
    __shared__ float Bs[16][132];
    int row0 = blockIdx.y * 128, col0 = blockIdx.x * 128;
    int tid = threadIdx.x;
    int rA = tid >> 2, k4 = (tid & 3) * 4;
    int ty = tid >> 4, tx = tid & 15;
    float cc[8][8] = {};
    for (int k0 = 0; k0 < Dn; k0 += 16) {
        float4 va = *(const float4*)&x[(size_t)(row0 + rA) * Dn + k0 + k4];
        As[k4 + 0][rA] = va.x; As[k4 + 1][rA] = va.y;
        As[k4 + 2][rA] = va.z; As[k4 + 3][rA] = va.w;
        float4 vb = *(const float4*)&x[(size_t)(row0 + rA + 64) * Dn + k0 + k4];
        As[k4 + 0][rA + 64] = vb.x; As[k4 + 1][rA + 64] = vb.y;
        As[k4 + 2][rA + 64] = vb.z; As[k4 + 3][rA + 64] = vb.w;
        float4 w0 = *(const float4*)&W[(size_t)(col0 + rA) * Dn + k0 + k4];
        Bs[k4 + 0][rA] = w0.x; Bs[k4 + 1][rA] = w0.y;
        Bs[k4 + 2][rA] = w0.z; Bs[k4 + 3][rA] = w0.w;
        float4 w1v = *(const float4*)&W[(size_t)(col0 + rA + 64) * Dn + k0 + k4];
        Bs[k4 + 0][rA + 64] = w1v.x; Bs[k4 + 1][rA + 64] = w1v.y;
        Bs[k4 + 2][rA + 64] = w1v.z; Bs[k4 + 3][rA + 64] = w1v.w;
        __syncthreads();
#pragma unroll
        for (int k = 0; k < 16; k++) {
            float4 a0 = *(float4*)&As[k][ty * 8], a1 = *(float4*)&As[k][ty * 8 + 4];
            float4 b0 = *(float4*)&Bs[k][tx * 8], b1 = *(float4*)&Bs[k][tx * 8 + 4];
            float ra[8] = {a0.x, a0.y, a0.z, a0.w, a1.x, a1.y, a1.z, a1.w};
            float rb[8] = {b0.x, b0.y, b0.z, b0.w, b1.x, b1.y, b1.z, b1.w};
#pragma unroll
            for (int i = 0; i < 8; i++)
#pragma unroll
                for (int j = 0; j < 8; j++) cc[i][j] += ra[i] * rb[j];
        }
        __syncthreads();
    }
#pragma unroll
    for (int i = 0; i < 8; i++) {
        float* c = &g_lin[(size_t)(row0 + ty * 8 + i) * Dn + col0 + tx * 8];
#pragma unroll
        for (int j = 0; j < 8; j++) c[j] = cc[i][j] + bias[col0 + tx * 8 + j];
    }
}

// ---------------- gate: exact fp32 top-2 ----------------
__global__ void k_gate(const float* __restrict__ Wg) {
    int warp = (blockIdx.x * blockDim.x + threadIdx.x) >> 5;
    int lane = threadIdx.x & 31;
    if (warp >= Tn) return;
    const float* lr = &g_lin[(size_t)warp * Dn];
    float p[En] = {};
    for (int i = lane; i < Dn; i += 32) {
        float v = lr[i];
        const float* w = &Wg[i * En];
#pragma unroll
        for (int e = 0; e < En; e++) p[e] += v * w[e];
    }
#pragma unroll
    for (int o = 16; o; o >>= 1)
#pragma unroll
        for (int e = 0; e < En; e++) p[e] += __shfl_xor_sync(0xffffffffu, p[e], o);
    if (lane == 0) {
        int i1 = 0;
        for (int e = 1; e < En; e++) if (p[e] > p[i1]) i1 = e;
        int i2 = -1;
        for (int e = 0; e < En; e++)
            if (e != i1 && (i2 < 0 || p[e] > p[i2])) i2 = e;
        float w1 = 1.f / (1.f + expf(p[i2] - p[i1]));
        g_gi[warp * 2] = i1; g_gi[warp * 2 + 1] = i2;
        g_gw[warp * 2] = w1; g_gw[warp * 2 + 1] = 1.f - w1;
        atomicAdd(&g_cnt[i1], 1);
        atomicAdd(&g_cnt[i2], 1);
    }
}

__global__ void k_off() {
    int a = 0;
    for (int e = 0; e < En; e++) { g_off[e] = a; a += g_cnt[e]; g_fill[e] = 0; }
}

__global__ void k_scatter() {
    int t = blockIdx.x * blockDim.x + threadIdx.x;
    if (t >= Tn) return;
#pragma unroll
    for (int k = 0; k < 2; k++) {
        int e = g_gi[t * 2 + k];
        int slot = g_off[e] + atomicAdd(&g_fill[e], 1);
        g_tok[slot] = t;
        g_tw[slot]  = g_gw[t * 2 + k];
    }
}

// ========== tf32 mma.sync grouped GEMM: 128x128 tile, 8 warps (4Mx2N) ======
// MODE 1: g_h = relu(lin[g_tok] @ w1[e] + b1)   (KD=Dn, NT=Fn)
// MODE 2: g_accb += gw * (g_h @ w2[e] + b2)     (KD=Fn, NT=Dn)
template<int KD, int NT, int MODE>
__global__ void __launch_bounds__(256) mma_ffn(const float* __restrict__ Bw,
                                               const float* __restrict__ bias)
{
    __shared__ float As[16][136];   // [k][m], pad 136 -> conflict-free frag lds
    __shared__ float Bs[16][136];   // [k][n]
    int e = blockIdx.z, cnt = g_cnt[e], row0 = blockIdx.x * 128;
    if (row0 >= cnt) return;
    int off = g_off[e], col0 = blockIdx.y * 128;
    int tid = threadIdx.x;
    int warp = tid >> 5, lane = tid & 31;
    int warpM = warp >> 1, warpN = warp & 1;
    int grp = lane >> 2, tig = lane & 3;
    int mBase = warpM * 32, nBase = warpN * 64;

    // staging indices (round-1 layout)
    int rA = tid >> 2, k4 = (tid & 3) * 4;
    const float *a0p, *a1p;
    if (MODE == 1) {
        bool v0 = (row0 + rA) < cnt, v1 = (row0 + rA + 64) < cnt;
        a0p = &g_lin[(size_t)(v0 ? g_tok[off + row0 + rA] : 0) * KD];
        a1p = &g_lin[(size_t)(v1 ? g_tok[off + row0 + rA + 64] : 0) * KD];
    } else {
        int s0 = off + row0 + rA;      if (s0 >= 2 * Tn) s0 = 0;
        int s1 = off + row0 + rA + 64; if (s1 >= 2 * Tn) s1 = 0;
        a0p = &g_h[(size_t)s0 * KD];
        a1p = &g_h[(size_t)s1 * KD];
    }
    const float* wp = Bw + (size_t)e * KD * NT;   // [K][NT], N contiguous

    float cc[2][8][4] = {};
    for (int k0 = 0; k0 < KD; k0 += 16) {
        float4 va = *(const float4*)&a0p[k0 + k4];
        As[k4 + 0][rA] = tf32r(va.x); As[k4 + 1][rA] = tf32r(va.y);
        As[k4 + 2][rA] = tf32r(va.z); As[k4 + 3][rA] = tf32r(va.w);
        float4 vb = *(const float4*)&a1p[k0 + k4];
        As[k4 + 0][rA + 64] = tf32r(vb.x); As[k4 + 1][rA + 64] = tf32r(vb.y);
        As[k4 + 2][rA + 64] = tf32r(vb.z); As[k4 + 3][rA + 64] = tf32r(vb.w);
#pragma unroll
        for (int l = 0; l < 2; l++) {
            int idx = tid + l * 256;
            int r = idx >> 5, c4 = (idx & 31) * 4;
            float4 v = *(const float4*)&wp[(size_t)(k0 + r) * NT + col0 + c4];
            Bs[r][c4 + 0] = tf32r(v.x); Bs[r][c4 + 1] = tf32r(v.y);
            Bs[r][c4 + 2] = tf32r(v.z); Bs[r][c4 + 3] = tf32r(v.w);
        }
        __syncthreads();
#pragma unroll
        for (int ks = 0; ks < 16; ks += 8) {
            uint32_t af[2][4];
#pragma unroll
            for (int mt = 0; mt < 2; mt++) {
                int m = mBase + mt * 16 + grp;
                af[mt][0] = __float_as_uint(As[ks + tig][m]);
                af[mt][1] = __float_as_uint(As[ks + tig][m + 8]);
                af[mt][2] = __float_as_uint(As[ks + tig + 4][m]);
                af[mt][3] = __float_as_uint(As[ks + tig + 4][m + 8]);
            }
#pragma unroll
            for (int nt = 0; nt < 8; nt++) {
                int n = nBase + nt * 8 + grp;
                uint32_t b0 = __float_as_uint(Bs[ks + tig][n]);
                uint32_t b1 = __float_as_uint(Bs[ks + tig + 4][n]);
                mma8(cc[0][nt], af[0], b0, b1);
                mma8(cc[1][nt], af[1], b0, b1);
            }
        }
        __syncthreads();
    }

    // epilogue: c0,c1 -> row grp; c2,c3 -> row grp+8; cols 2*tig, 2*tig+1
#pragma unroll
    for (int mt = 0; mt < 2; mt++) {
#pragma unroll
        for (int half = 0; half < 2; half++) {
            int r = row0 + mBase + mt * 16 + grp + half * 8;
            if (r >= cnt) continue;
            int slot = off + r;
            if (MODE == 1) {
                float* o = g_h + (size_t)slot * Fn + col0;
#pragma unroll
                for (int nt = 0; nt < 8; nt++) {
                    int c = nBase + nt * 8 + 2 * tig;
                    float2 v;
                    v.x = fmaxf(cc[mt][nt][half * 2 + 0] + bias[e * Fn + col0 + c], 0.f);
                    v.y = fmaxf(cc[mt][nt][half * 2 + 1] + bias[e * Fn + col0 + c + 1], 0.f);
                    *(float2*)(o + c) = v;
                }
            } else {
                int tok = g_tok[slot];
                float gw = g_tw[slot];
                float* o = g_accb + (size_t)tok * Dn + col0;
#pragma unroll
                for (int nt = 0; nt < 8; nt++) {
                    int c = nBase + nt * 8 + 2 * tig;
                    atomicAdd(&o[c],     gw * (cc[mt][nt][half * 2 + 0] + bias[e * Dn + col0 + c]));
                    atomicAdd(&o[c + 1], gw * (cc[mt][nt][half * 2 + 1] + bias[e * Dn + col0 + c + 1]));
                }
            }
        }
    }
}

// ---------------- mean pool + loss ----------------
__global__ void k_sent(float* out) {
    int i = blockIdx.x * blockDim.x + threadIdx.x;
    if (i == 0) out[0] = 0.f;
    if (i >= Bb * Dn) return;
    int b = i >> 10, d = i & 1023;
    const float* p = &g_accb[(size_t)(b * Sn) * Dn + d];
    float s = 0.f;
    for (int si = 0; si < Sn; si++) s += p[si * Dn];
    g_sent[i] = s * (1.f / Sn);
}

__global__ void k_loss(const int* __restrict__ y, float* out) {
    int b = blockIdx.x, tid = threadIdx.x;
    __shared__ float red[256];
    const float* s = &g_sent[b * Dn];
    float m = -1e30f;
    for (int i = tid; i < Dn; i += 256) m = fmaxf(m, s[i]);
    red[tid] = m; __syncthreads();
    for (int o = 128; o; o >>= 1) {
        if (tid < o) red[tid] = fmaxf(red[tid], red[tid + o]);
        __syncthreads();
    }
    float mx = red[0]; __syncthreads();
    float sum = 0.f;
    for (int i = tid; i < Dn; i += 256) sum += expf(s[i] - mx);
    red[tid] = sum; __syncthreads();
    for (int o = 128; o; o >>= 1) {
        if (tid < o) red[tid] += red[tid + o];
        __syncthreads();
    }
    if (tid == 0)
        atomicAdd(out, -(s[y[b]] - (mx + logf(red[0]))) * (1.f / Bb));
}

// ---------------- launch ----------------
extern "C" void kernel_launch(void* const* d_in, const int* in_sizes, int n_in,
                              void* d_out, int out_size) {
    const float* x  = (const float*)d_in[0];
    const int*   y  = (const int*)d_in[1];
    const float* W  = (const float*)d_in[2];
    const float* bb = (const float*)d_in[3];
    const float* Wg = (const float*)d_in[4];
    const float* w1 = (const float*)d_in[5];
    const float* b1 = (const float*)d_in[6];
    const float* w2 = (const float*)d_in[7];
    const float* b2 = (const float*)d_in[8];
    float* out = (float*)d_out;

    k_init<<<256, 256>>>(x);
    k_gemm_lin<<<dim3(Dn / 128, Tn / 128), 256>>>(x, W, bb);
    k_gate<<<(Tn * 32) / 256, 256>>>(Wg);
    k_off<<<1, 1>>>();
    k_scatter<<<Tn / 256, 256>>>();
    mma_ffn<Dn, Fn, 1><<<dim3(Tn / 128, Fn / 128, En), 256>>>(w1, b1);
    mma_ffn<Fn, Dn, 2><<<dim3(Tn / 128, Dn / 128, En), 256>>>(w2, b2);
    k_sent<<<(Bb * Dn + 255) / 256, 256>>>(out);
    k_loss<<<Bb, 256>>>(y, out);
}